// round 1
// baseline (speedup 1.0000x reference)
#include <cuda_runtime.h>

// DySample: B=16, C=64, H=W=128, scale=2, groups=4
// out[b, g*16+cc, 2h+ri, 2w+rj] = bilinear(x[b, g*16+cc], iy, ix)
//   ix = clamp(w + off[b, g*4+ri*2+rj,    h, w], 0, 127)
//   iy = clamp(h + off[b, 16+g*4+ri*2+rj, h, w], 0, 127)
//   off = (x . w_off^T + b_off) * 0.25 + init_pos

#define BB 16
#define CC 64
#define HH 128
#define WW 128
#define HW (HH * WW)

// scratch: offsets [B, 32, H, W] = 8.4M floats (33.5 MB)
__device__ __align__(16) float g_offs[BB * 32 * HW];

// ---------------------------------------------------------------------------
// Kernel 1: per-pixel 64->32 matvec (offsets), register-tiled.
// grid (H, B), block 128. Thread tile: 8 pixels x 4 out-channels.
// ---------------------------------------------------------------------------
__global__ __launch_bounds__(128) void offsets_kernel(
    const float* __restrict__ x,
    const float* __restrict__ w_off,
    const float* __restrict__ b_off)
{
    __shared__ __align__(16) float xs[64 * 128];  // [c][w]
    __shared__ __align__(16) float ws[64 * 32];   // [c][o]

    const int h   = blockIdx.x;
    const int b   = blockIdx.y;
    const int tid = threadIdx.x;

    // Load x row (all 64 channels, 128 pixels), coalesced.
    const float* xb = x + ((b * 64) << 14) + (h << 7);
    #pragma unroll
    for (int i = tid; i < 64 * 128; i += 128) {
        int c = i >> 7, w = i & 127;
        xs[i] = xb[(c << 14) + w];
    }
    // Weights: w_off is [o=32][c=64] row-major -> ws[c][o].
    for (int i = tid; i < 2048; i += 128) {
        int c = i >> 5, o = i & 31;
        ws[i] = __ldg(&w_off[o * 64 + c]);
    }
    __syncthreads();

    const int w0 = (tid & 15) * 8;   // 8 consecutive pixels
    const int ob = (tid >> 4) * 4;   // 4 consecutive out-channels

    float acc[8][4];
    #pragma unroll
    for (int p = 0; p < 8; p++)
        #pragma unroll
        for (int oo = 0; oo < 4; oo++) acc[p][oo] = 0.0f;

    #pragma unroll 4
    for (int c = 0; c < 64; c++) {
        const float4 xa = *(const float4*)&xs[c * 128 + w0];
        const float4 xc = *(const float4*)&xs[c * 128 + w0 + 4];
        const float4 wv = *(const float4*)&ws[c * 32 + ob];
        const float xv[8] = {xa.x, xa.y, xa.z, xa.w, xc.x, xc.y, xc.z, xc.w};
        const float wr[4] = {wv.x, wv.y, wv.z, wv.w};
        #pragma unroll
        for (int p = 0; p < 8; p++)
            #pragma unroll
            for (int oo = 0; oo < 4; oo++)
                acc[p][oo] = fmaf(xv[p], wr[oo], acc[p][oo]);
    }

    float* dst = g_offs + ((b * 32) << 14) + (h << 7);
    #pragma unroll
    for (int oo = 0; oo < 4; oo++) {
        const int o = ob + oo;
        const float bias = __ldg(&b_off[o]);
        // init_pos: o = g'*8 + d'*4 + i*2 + j ; val = 0.25*(2*(d'? i : j) - 1)
        const int dd = (o >> 2) & 1;
        const int ii = (o >> 1) & 1;
        const int jj = o & 1;
        const float initv = 0.25f * (float)(((dd ? ii : jj) << 1) - 1);
        #pragma unroll
        for (int p = 0; p < 8; p += 4) {
            float4 v;
            v.x = (acc[p + 0][oo] + bias) * 0.25f + initv;
            v.y = (acc[p + 1][oo] + bias) * 0.25f + initv;
            v.z = (acc[p + 2][oo] + bias) * 0.25f + initv;
            v.w = (acc[p + 3][oo] + bias) * 0.25f + initv;
            *(float4*)&dst[(o << 14) + w0 + p] = v;
        }
    }
}

// ---------------------------------------------------------------------------
// Kernel 2: bilinear sampling.
// grid (H, B), block 256: thread = output X column (0..255).
// Covers Y in {2h, 2h+1}, all 64 channels -> 128 outputs/thread.
// Position (ix, iy, weights, tap indices) computed once per (g, ri),
// reused across 16 channels.
// ---------------------------------------------------------------------------
__global__ __launch_bounds__(256) void sample_kernel(
    const float* __restrict__ x,
    float* __restrict__ out)
{
    const int h  = blockIdx.x;
    const int b  = blockIdx.y;
    const int X  = threadIdx.x;   // 0..255
    const int w  = X >> 1;
    const int rj = X & 1;

    const float* offb = g_offs + ((b * 32) << 14) + (h << 7) + w;
    const float fw = (float)w;
    const float fh = (float)h;

    #pragma unroll
    for (int g = 0; g < 4; g++) {
        const float* src = x + (((b * 64 + g * 16)) << 14);
        #pragma unroll
        for (int ri = 0; ri < 2; ri++) {
            const int o = g * 4 + ri * 2 + rj;
            const float offx = __ldg(&offb[o << 14]);
            const float offy = __ldg(&offb[(o + 16) << 14]);

            const float ix = fminf(fmaxf(fw + offx, 0.0f), 127.0f);
            const float iy = fminf(fmaxf(fh + offy, 0.0f), 127.0f);
            const float x0f = floorf(ix), y0f = floorf(iy);
            const float wx = ix - x0f, wy = iy - y0f;
            const int x0 = (int)x0f, y0 = (int)y0f;
            const int x1 = min(x0 + 1, 127);
            const int y1 = min(y0 + 1, 127);

            const float w00 = (1.0f - wy) * (1.0f - wx);
            const float w01 = (1.0f - wy) * wx;
            const float w10 = wy * (1.0f - wx);
            const float w11 = wy * wx;

            const int i00 = (y0 << 7) + x0;
            const int i01 = (y0 << 7) + x1;
            const int i10 = (y1 << 7) + x0;
            const int i11 = (y1 << 7) + x1;

            const int Y = (h << 1) + ri;
            float* dst = out + (((b * 64 + g * 16) * 256 + Y) << 8) + X;
            const float* p = src;
            #pragma unroll
            for (int cc = 0; cc < 16; cc++) {
                const float v = fmaf(w00, __ldg(p + i00),
                                fmaf(w01, __ldg(p + i01),
                                fmaf(w10, __ldg(p + i10),
                                     w11 * __ldg(p + i11))));
                *dst = v;
                p   += HW;
                dst += 65536;   // 256*256
            }
        }
    }
}

extern "C" void kernel_launch(void* const* d_in, const int* in_sizes, int n_in,
                              void* d_out, int out_size)
{
    const float* x     = (const float*)d_in[0];  // [16,64,128,128]
    const float* w_off = (const float*)d_in[1];  // [32,64]
    const float* b_off = (const float*)d_in[2];  // [32]
    float* out = (float*)d_out;                  // [16,64,256,256]

    offsets_kernel<<<dim3(HH, BB), 128>>>(x, w_off, b_off);
    sample_kernel<<<dim3(HH, BB), 256>>>(x, out);
    (void)in_sizes; (void)n_in; (void)out_size;
}